// round 12
// baseline (speedup 1.0000x reference)
#include <cuda_runtime.h>
#include <cuda_bf16.h>
#include <cstdint>

#define N_NODES 50000
#define N_EDGES 800000
#define C_HID   512
#define C_OUT   256
#define WSZ     (C_HID * C_HID)

// ------------------------- scratch (device globals; no allocation) ----------
__device__ __align__(256) int   g_cnt[N_NODES];
__device__ __align__(256) int   g_rowstart[N_NODES + 1];
__device__ __align__(256) int   g_cursor[N_NODES];
__device__ __align__(256) float g_dinv[N_NODES];
__device__ __align__(256) int   g_csr_src[N_EDGES];
__device__ __align__(256) float g_csr_w[N_EDGES];
__device__ __align__(256) float g_H[(size_t)N_NODES * C_HID];
__device__ __align__(256) float g_G[(size_t)N_NODES * C_HID];
__device__ __align__(256) int8_t g_Qa1[(size_t)N_NODES * C_HID];
__device__ __align__(256) int8_t g_Qa2[(size_t)N_NODES * C_HID];
__device__ __align__(256) int8_t g_Qb1[3][WSZ];   // [N][K] k-contiguous
__device__ __align__(256) int8_t g_Qb2[3][WSZ];
__device__ __align__(256) float g_arow[N_NODES];  // A row scales (s1)
__device__ __align__(256) float g_bs[3][C_HID];   // B col scales (s1)
__device__ int g_is64;

// ------------------------- small helpers ------------------------------------
__device__ __forceinline__ uint32_t smem_u32(const void* p) {
    return (uint32_t)__cvta_generic_to_shared(p);
}

__device__ __forceinline__ void cp_async16(uint32_t saddr, const void* gptr, int src_size) {
    asm volatile("cp.async.cg.shared.global [%0], [%1], 16, %2;\n"
                 :: "r"(saddr), "l"(gptr), "r"(src_size));
}

__device__ __forceinline__ void imma_16832(int* c, const uint32_t* a, const uint32_t* b) {
    asm volatile(
        "mma.sync.aligned.m16n8k32.row.col.s32.s8.s8.s32 "
        "{%0,%1,%2,%3},{%4,%5,%6,%7},{%8,%9},{%0,%1,%2,%3};"
        : "+r"(c[0]), "+r"(c[1]), "+r"(c[2]), "+r"(c[3])
        : "r"(a[0]), "r"(a[1]), "r"(a[2]), "r"(a[3]), "r"(b[0]), "r"(b[1]));
}

__device__ __forceinline__ int load_idx(const void* ei, long long pos, int is64) {
    if (is64) return (int)((const long long*)ei)[pos];
    return ((const int*)ei)[pos];
}

__device__ __forceinline__ int clamp127(int q) {
    return q < -127 ? -127 : (q > 127 ? 127 : q);
}

__device__ __forceinline__ uint32_t pack4(int a, int b, int c, int d) {
    return (uint32_t)(a & 255) | ((uint32_t)(b & 255) << 8) |
           ((uint32_t)(c & 255) << 16) | ((uint32_t)(d & 255) << 24);
}

// ------------------------- graph preprocessing kernels ----------------------
__global__ void detect_kernel(const int* __restrict__ ei32) {
    if (threadIdx.x == 0) {
        int is64 = 1;
        for (int k = 1; k < 512; k += 2)
            if (ei32[k] != 0) { is64 = 0; break; }
        g_is64 = is64;
    }
}

__global__ void zero_kernel() {
    int i = blockIdx.x * blockDim.x + threadIdx.x;
    if (i < N_NODES) { g_cnt[i] = 0; g_cursor[i] = 0; }
}

__global__ void deg_kernel(const void* __restrict__ ei) {
    int e = blockIdx.x * blockDim.x + threadIdx.x;
    if (e >= N_EDGES) return;
    int is64 = g_is64;
    int d = load_idx(ei, (long long)N_EDGES + e, is64);
    atomicAdd(&g_cnt[d], 1);
}

__global__ void dinv_kernel() {
    int i = blockIdx.x * blockDim.x + threadIdx.x;
    if (i < N_NODES) g_dinv[i] = rsqrtf((float)(g_cnt[i] + 1));
}

__global__ void scan_kernel() {
    __shared__ int s[1024];
    const int CHK = (N_NODES + 1023) / 1024;
    int t = threadIdx.x;
    int base = t * CHK;
    int sum = 0;
    for (int j = 0; j < CHK; j++) {
        int i = base + j;
        if (i < N_NODES) sum += g_cnt[i];
    }
    s[t] = sum;
    __syncthreads();
    for (int off = 1; off < 1024; off <<= 1) {
        int v = (t >= off) ? s[t - off] : 0;
        __syncthreads();
        s[t] += v;
        __syncthreads();
    }
    int run = (t == 0) ? 0 : s[t - 1];
    for (int j = 0; j < CHK; j++) {
        int i = base + j;
        if (i < N_NODES) { g_rowstart[i] = run; run += g_cnt[i]; }
    }
    if (t == 1023) g_rowstart[N_NODES] = run;
}

__global__ void scatter_kernel(const void* __restrict__ ei) {
    int e = blockIdx.x * blockDim.x + threadIdx.x;
    if (e >= N_EDGES) return;
    int is64 = g_is64;
    int s = load_idx(ei, e, is64);
    int d = load_idx(ei, (long long)N_EDGES + e, is64);
    int pos = g_rowstart[d] + atomicAdd(&g_cursor[d], 1);
    g_csr_src[pos] = s;
    g_csr_w[pos]   = g_dinv[s] * g_dinv[d];
}

// ------------------------- quantization helpers ------------------------------
// shared 128-thread max reduce; every thread returns the block max
__device__ __forceinline__ float blockmax128(float v, float* s_red, int t) {
    s_red[t] = v;
    __syncthreads();
#pragma unroll
    for (int s = 64; s > 0; s >>= 1) {
        if (t < s) s_red[t] = fmaxf(s_red[t], s_red[t + s]);
        __syncthreads();
    }
    float m = s_red[0];
    __syncthreads();
    return m;
}

// quantize 4 values with row scale; emit two packed int8 words
__device__ __forceinline__ void quant4(const float* v, float s1, float is1,
                                       uint32_t& w1, uint32_t& w2) {
    float is2 = is1 * 128.0f;
    int q1[4], q2[4];
#pragma unroll
    for (int j = 0; j < 4; j++) {
        q1[j] = clamp127(__float2int_rn(v[j] * is1));
        float r = fmaf((float)(-q1[j]), s1, v[j]);
        q2[j] = clamp127(__float2int_rn(r * is2));
    }
    w1 = pack4(q1[0], q1[1], q1[2], q1[3]);
    w2 = pack4(q2[0], q2[1], q2[2], q2[3]);
}

// x (first-layer input) quantization: one block per row
__global__ void xquant_kernel(const float* __restrict__ x) {
    __shared__ float s_red[128];
    int i = blockIdx.x;
    int t = threadIdx.x;
    float4 v4 = *(const float4*)(x + (size_t)i * C_HID + t * 4);
    float v[4] = {v4.x, v4.y, v4.z, v4.w};
    float am = fmaxf(fmaxf(fabsf(v[0]), fabsf(v[1])), fmaxf(fabsf(v[2]), fabsf(v[3])));
    float amax = blockmax128(am, s_red, t);
    float s1  = amax * (1.0f / 127.0f);
    float is1 = amax > 0.f ? 127.0f / amax : 0.f;
    uint32_t w1, w2;
    quant4(v, s1, is1, w1, w2);
    ((uint32_t*)(g_Qa1 + (size_t)i * C_HID))[t] = w1;
    ((uint32_t*)(g_Qa2 + (size_t)i * C_HID))[t] = w2;
    if (t == 0) g_arow[i] = s1;
}

// weight quantization: one block per output column n; W is [K,N] row-major.
// Writes QbT [n][k] (k-contiguous) 2-chunk int8 + column scale.
__global__ void wquant_kernel(const float* __restrict__ W, int N,
                              int8_t* __restrict__ Qb1, int8_t* __restrict__ Qb2,
                              float* __restrict__ bs) {
    __shared__ float s_red[128];
    int n = blockIdx.x;
    int t = threadIdx.x;
    float v[4];
#pragma unroll
    for (int j = 0; j < 4; j++) v[j] = W[(size_t)(4 * t + j) * N + n];
    float am = fmaxf(fmaxf(fabsf(v[0]), fabsf(v[1])), fmaxf(fabsf(v[2]), fabsf(v[3])));
    float amax = blockmax128(am, s_red, t);
    float s1  = amax * (1.0f / 127.0f);
    float is1 = amax > 0.f ? 127.0f / amax : 0.f;
    uint32_t w1, w2;
    quant4(v, s1, is1, w1, w2);
    ((uint32_t*)(Qb1 + (size_t)n * C_HID))[t] = w1;
    ((uint32_t*)(Qb2 + (size_t)n * C_HID))[t] = w2;
    if (t == 0) bs[n] = s1;
}

// ------------------------- int8 2-chunk GEMM ---------------------------------
// C[M,N] = sum over k of dequant(A)·dequant(B^T):
//   P11 = Qa1·Qb1 (s32), Pc = Qa2·Qb1 + Qa1·Qb2 (s32, shared accumulator)
//   C = sa1[m]·sb1[n]·(P11 + Pc·2^-7)       (Qa2·Qb2 term dropped, ~3e-5 rel)
// Block tile 128x128, 8 warps (2x4), warp tile 64x32, k-tile 64 double-buffered.
#define QT_STRIDE 80              // 64 data bytes + 16 pad (conflict-free ldmatrix)
#define QTILE (128 * QT_STRIDE)   // bytes per (stage, chunk) tile
#define GEMM_SMEM (8 * QTILE)     // 2 stages * (2 A chunks + 2 B chunks) = 81920

__global__ __launch_bounds__(256) void gemm_i8(
    const int8_t* __restrict__ Qa1, const int8_t* __restrict__ Qa2,
    const int8_t* __restrict__ Qb1, const int8_t* __restrict__ Qb2,
    const float* __restrict__ arow, const float* __restrict__ bs,
    float* __restrict__ C, int M, int N)
{
    extern __shared__ __align__(16) uint8_t sm8[];
    uint8_t* As = sm8;                 // [st*2+chunk][128*80]
    uint8_t* Bs = sm8 + 4 * QTILE;

    const int tid  = threadIdx.x;
    const int lane = tid & 31;
    const int w    = tid >> 5;
    const int wr   = w >> 2;
    const int wc   = w & 3;
    const int m0   = blockIdx.x * 128;
    const int n0   = blockIdx.y * 128;

    int p11[4][4][4], pc[4][4][4];
#pragma unroll
    for (int a = 0; a < 4; a++)
#pragma unroll
        for (int b = 0; b < 4; b++)
#pragma unroll
            for (int c = 0; c < 4; c++) { p11[a][b][c] = 0; pc[a][b][c] = 0; }

    const int NIT = 8;   // K=512 / 64

    auto loadstage = [&](int it, int st) {
        int k0 = it << 6;
#pragma unroll
        for (int chunk = 0; chunk < 2; chunk++) {
            const int8_t* A = chunk ? Qa2 : Qa1;
            uint32_t dstA = smem_u32(As + (st * 2 + chunk) * QTILE);
#pragma unroll
            for (int r = 0; r < 2; r++) {       // A: 128 rows x 64 B
                int o = tid + r * 256;
                int row = o >> 2, seg = o & 3;
                int gr = m0 + row;
                int sz = (gr < M) ? 16 : 0;
                int grc = (gr < M) ? gr : (M - 1);
                cp_async16(dstA + row * QT_STRIDE + seg * 16,
                           A + (size_t)grc * 512 + k0 + seg * 16, sz);
            }
            const int8_t* B = chunk ? Qb2 : Qb1;
            uint32_t dstB = smem_u32(Bs + (st * 2 + chunk) * QTILE);
#pragma unroll
            for (int r = 0; r < 2; r++) {       // B: 128 rows x 64 B
                int o = tid + r * 256;
                int row = o >> 2, seg = o & 3;
                cp_async16(dstB + row * QT_STRIDE + seg * 16,
                           B + (size_t)(n0 + row) * 512 + k0 + seg * 16, 16);
            }
        }
        asm volatile("cp.async.commit_group;\n" ::);
    };

    loadstage(0, 0);
    for (int it = 0; it < NIT; it++) {
        int st = it & 1;
        if (it + 1 < NIT) {
            loadstage(it + 1, st ^ 1);
            asm volatile("cp.async.wait_group 1;\n" ::);
        } else {
            asm volatile("cp.async.wait_group 0;\n" ::);
        }
        __syncthreads();

#pragma unroll
        for (int ks = 0; ks < 2; ks++) {
            int kk = ks * 32;
            int lr = lane & 15;
            int lh = (lane >> 4) * 16;

            uint32_t a1[4][4], a2[4][4];
#pragma unroll
            for (int mt = 0; mt < 4; mt++) {
                int off = (wr * 64 + mt * 16 + lr) * QT_STRIDE + kk + lh;
                uint32_t addr = smem_u32(As + 0 * QTILE + st * 2 * QTILE) + off;
                asm volatile("ldmatrix.sync.aligned.m8n8.x4.shared.b16 {%0,%1,%2,%3},[%4];"
                             : "=r"(a1[mt][0]), "=r"(a1[mt][1]),
                               "=r"(a1[mt][2]), "=r"(a1[mt][3]) : "r"(addr));
                addr = smem_u32(As + (st * 2 + 1) * QTILE) + off;
                asm volatile("ldmatrix.sync.aligned.m8n8.x4.shared.b16 {%0,%1,%2,%3},[%4];"
                             : "=r"(a2[mt][0]), "=r"(a2[mt][1]),
                               "=r"(a2[mt][2]), "=r"(a2[mt][3]) : "r"(addr));
            }
            uint32_t b1[4][2], b2[4][2];
#pragma unroll
            for (int np = 0; np < 2; np++) {
                int off = (wc * 32 + np * 16 + lr) * QT_STRIDE + kk + lh;
                uint32_t r0, r1, r2, r3;
                uint32_t addr = smem_u32(Bs + st * 2 * QTILE) + off;
                asm volatile("ldmatrix.sync.aligned.m8n8.x4.shared.b16 {%0,%1,%2,%3},[%4];"
                             : "=r"(r0), "=r"(r1), "=r"(r2), "=r"(r3) : "r"(addr));
                b1[np * 2][0] = r0; b1[np * 2][1] = r2;
                b1[np * 2 + 1][0] = r1; b1[np * 2 + 1][1] = r3;
                addr = smem_u32(Bs + (st * 2 + 1) * QTILE) + off;
                asm volatile("ldmatrix.sync.aligned.m8n8.x4.shared.b16 {%0,%1,%2,%3},[%4];"
                             : "=r"(r0), "=r"(r1), "=r"(r2), "=r"(r3) : "r"(addr));
                b2[np * 2][0] = r0; b2[np * 2][1] = r2;
                b2[np * 2 + 1][0] = r1; b2[np * 2 + 1][1] = r3;
            }
#pragma unroll
            for (int mt = 0; mt < 4; mt++)
#pragma unroll
                for (int nt = 0; nt < 4; nt++) {
                    imma_16832(p11[mt][nt], a1[mt], b1[nt]);
                    imma_16832(pc[mt][nt],  a2[mt], b1[nt]);
                    imma_16832(pc[mt][nt],  a1[mt], b2[nt]);
                }
        }
        __syncthreads();
    }

    // epilogue: dequantize and store fp32
    int g  = lane >> 2;
    int tq = lane & 3;
#pragma unroll
    for (int mt = 0; mt < 4; mt++) {
        int r0 = m0 + wr * 64 + mt * 16 + g;
        float sa0 = (r0 < M) ? arow[r0] : 0.f;
        float sa1 = (r0 + 8 < M) ? arow[r0 + 8] : 0.f;
#pragma unroll
        for (int nt = 0; nt < 4; nt++) {
            int col = n0 + wc * 32 + nt * 8 + tq * 2;
            float sb0 = bs[col], sb1 = bs[col + 1];
            float f0 = (float)p11[mt][nt][0] + (float)pc[mt][nt][0] * 0.0078125f;
            float f1 = (float)p11[mt][nt][1] + (float)pc[mt][nt][1] * 0.0078125f;
            float f2 = (float)p11[mt][nt][2] + (float)pc[mt][nt][2] * 0.0078125f;
            float f3 = (float)p11[mt][nt][3] + (float)pc[mt][nt][3] * 0.0078125f;
            if (r0 < M) {
                C[(size_t)r0 * N + col]     = sa0 * sb0 * f0;
                C[(size_t)r0 * N + col + 1] = sa0 * sb1 * f1;
            }
            if (r0 + 8 < M) {
                C[(size_t)(r0 + 8) * N + col]     = sa1 * sb0 * f2;
                C[(size_t)(r0 + 8) * N + col + 1] = sa1 * sb1 * f3;
            }
        }
    }
}

// ------------------------- propagation (gather-CSR) + fused quant -----------
template <int CH, bool RELU, bool RES, bool QUANT>
__global__ void prop_kernel(const float* __restrict__ G,
                            const float* __restrict__ bias,
                            float* __restrict__ out) {
    constexpr int V = CH / 128;
    __shared__ int   s_src[128];
    __shared__ float s_w[128];
    __shared__ float s_red[128];

    int i = blockIdx.x;
    int t = threadIdx.x;
    int c = t * V;

    float di = g_dinv[i];
    float sw = di * di;
    float acc[V];
    const float* gi = G + (size_t)i * CH + c;
    if constexpr (V == 4) {
        float4 v = *(const float4*)gi;
        acc[0] = sw * v.x; acc[1] = sw * v.y; acc[2] = sw * v.z; acc[3] = sw * v.w;
    } else {
        float2 v = *(const float2*)gi;
        acc[0] = sw * v.x; acc[1] = sw * v.y;
    }

    int beg = g_rowstart[i];
    int end = g_rowstart[i + 1];
    for (int e0 = beg; e0 < end; e0 += 128) {
        int n = end - e0;
        if (n > 128) n = 128;
        __syncthreads();
        if (t < n) {
            s_src[t] = g_csr_src[e0 + t];
            s_w[t]   = g_csr_w[e0 + t];
        }
        __syncthreads();
        for (int j = 0; j < n; j++) {
            float wv = s_w[j];
            const float* r = G + (size_t)s_src[j] * CH + c;
            if constexpr (V == 4) {
                float4 v = *(const float4*)r;
                acc[0] += wv * v.x; acc[1] += wv * v.y;
                acc[2] += wv * v.z; acc[3] += wv * v.w;
            } else {
                float2 v = *(const float2*)r;
                acc[0] += wv * v.x; acc[1] += wv * v.y;
            }
        }
    }

    float* o = out + (size_t)i * CH + c;
    float res[V];
#pragma unroll
    for (int j = 0; j < V; j++) {
        float v = acc[j] + bias[c + j];
        if (RELU) v = v > 0.f ? v : 0.f;
        if (RES) v += o[j];  // out aliases H: read old value before overwrite
        o[j] = v;
        res[j] = v;
    }
    if constexpr (QUANT) {   // V == 4 here
        __syncthreads();     // s_src/s_w reuse done; protect s_red usage
        float am = fmaxf(fmaxf(fabsf(res[0]), fabsf(res[1])),
                         fmaxf(fabsf(res[2]), fabsf(res[3])));
        float amax = blockmax128(am, s_red, t);
        float s1  = amax * (1.0f / 127.0f);
        float is1 = amax > 0.f ? 127.0f / amax : 0.f;
        uint32_t w1, w2;
        quant4(res, s1, is1, w1, w2);
        ((uint32_t*)(g_Qa1 + (size_t)i * CH))[t] = w1;
        ((uint32_t*)(g_Qa2 + (size_t)i * CH))[t] = w2;
        if (t == 0) g_arow[i] = s1;
    }
}

// ------------------------- driver -------------------------------------------
extern "C" void kernel_launch(void* const* d_in, const int* in_sizes, int n_in,
                              void* d_out, int out_size) {
    (void)in_sizes; (void)n_in; (void)out_size;
    const float* x   = (const float*)d_in[0];
    const void*  ei  = d_in[1];
    const float* W1  = (const float*)d_in[2];
    const float* b1  = (const float*)d_in[3];
    const float* Wr  = (const float*)d_in[4];
    const float* br  = (const float*)d_in[5];
    const float* Wx  = (const float*)d_in[6];
    const float* bx  = (const float*)d_in[7];
    float*       out = (float*)d_out;

    void* p;
    cudaGetSymbolAddress(&p, g_H);    float* H = (float*)p;
    cudaGetSymbolAddress(&p, g_G);    float* G = (float*)p;
    cudaGetSymbolAddress(&p, g_Qa1);  int8_t* Qa1 = (int8_t*)p;
    cudaGetSymbolAddress(&p, g_Qa2);  int8_t* Qa2 = (int8_t*)p;
    cudaGetSymbolAddress(&p, g_Qb1);  int8_t* Qb1 = (int8_t*)p;
    cudaGetSymbolAddress(&p, g_Qb2);  int8_t* Qb2 = (int8_t*)p;
    cudaGetSymbolAddress(&p, g_arow); float* arow = (float*)p;
    cudaGetSymbolAddress(&p, g_bs);   float* bs = (float*)p;

    static int smem_set = 0;
    if (!smem_set) {
        cudaFuncSetAttribute(gemm_i8,
                             cudaFuncAttributeMaxDynamicSharedMemorySize, GEMM_SMEM);
        smem_set = 1;
    }

    // graph preprocessing
    detect_kernel<<<1, 32>>>((const int*)ei);
    zero_kernel<<<(N_NODES + 255) / 256, 256>>>();
    deg_kernel<<<(N_EDGES + 255) / 256, 256>>>(ei);
    dinv_kernel<<<(N_NODES + 255) / 256, 256>>>();
    scan_kernel<<<1, 1024>>>();
    scatter_kernel<<<(N_EDGES + 255) / 256, 256>>>(ei);

    // weight quantization (per-column, transposed to [N][K])
    wquant_kernel<<<C_HID, 128>>>(W1, C_HID, Qb1 + 0 * WSZ, Qb2 + 0 * WSZ, bs + 0 * C_HID);
    wquant_kernel<<<C_HID, 128>>>(Wr, C_HID, Qb1 + 1 * WSZ, Qb2 + 1 * WSZ, bs + 1 * C_HID);
    wquant_kernel<<<C_OUT, 128>>>(Wx, C_OUT, Qb1 + 2 * WSZ, Qb2 + 2 * WSZ, bs + 2 * C_HID);

    dim3 gg((N_NODES + 127) / 128, C_HID / 128);

    // layer 1: h = relu(P(x@W1) + b1); prop fuses int8 quantization of h
    xquant_kernel<<<N_NODES, 128>>>(x);
    gemm_i8<<<gg, 256, GEMM_SMEM>>>(Qa1, Qa2, Qb1 + 0 * WSZ, Qb2 + 0 * WSZ,
                                    arow, bs + 0 * C_HID, G, N_NODES, C_HID);
    prop_kernel<512, true, false, true><<<N_NODES, 128>>>(G, b1, H);

    // 4 shared residual layers: h = relu(P(h@Wr) + br) + h
    for (int d = 0; d < 4; d++) {
        gemm_i8<<<gg, 256, GEMM_SMEM>>>(Qa1, Qa2, Qb1 + 1 * WSZ, Qb2 + 1 * WSZ,
                                        arow, bs + 1 * C_HID, G, N_NODES, C_HID);
        prop_kernel<512, true, true, true><<<N_NODES, 128>>>(G, br, H);
    }

    // output layer: out = P(h@Wx) + bx
    dim3 g2((N_NODES + 127) / 128, C_OUT / 128);
    gemm_i8<<<g2, 256, GEMM_SMEM>>>(Qa1, Qa2, Qb1 + 2 * WSZ, Qb2 + 2 * WSZ,
                                    arow, bs + 2 * C_HID, G, N_NODES, C_OUT);
    prop_kernel<256, false, false, false><<<N_NODES, 128>>>(G, bx, out);
}